// round 17
// baseline (speedup 1.0000x reference)
#include <cuda_runtime.h>
#include <cuda_bf16.h>
#include <cstdint>

// TensorProductScatter: per-edge e3nn tensor product + scatter-add.
// R8 structure (warp-per-edge, natural order, smem staging, TMA bulk-reduce
// flush) + the 512 MB weight stream moved onto the TMA engine:
// each 256-thread block (8 warps = 8 consecutive edges) issues ONE
// cp.async.bulk of the block's contiguous 5120 B weight slab into SMEM
// (replacing 40 per-lane LDGs through L1tex), then warps read their 640 B
// via conflict-free LDS.

#define MULC 32
#define ROWF 352            // 32 + 96 + 96 + 32 + 96
#define WARPS_PER_BLOCK 8
#define WBYTES (5 * MULC * 4)                    // 640 B per edge
#define TILE_WBYTES (WARPS_PER_BLOCK * WBYTES)   // 5120 B per block

__device__ __forceinline__ uint32_t smem_u32(const void* p) {
    uint32_t a;
    asm("{ .reg .u64 t; cvta.to.shared.u64 t, %1; cvt.u32.u64 %0, t; }"
        : "=r"(a) : "l"(p));
    return a;
}

__global__ void tps_zero_kernel(float4* __restrict__ out, int n4) {
    int i = blockIdx.x * blockDim.x + threadIdx.x;
    if (i < n4) out[i] = make_float4(0.f, 0.f, 0.f, 0.f);
}

__global__ __launch_bounds__(WARPS_PER_BLOCK * 32)
void tps_scatter_kernel(const float* __restrict__ x,
                        const float* __restrict__ edge_attr,
                        const float* __restrict__ edge_weight,
                        const int*   __restrict__ edge_dst,
                        const int*   __restrict__ edge_src,
                        float*       __restrict__ out,
                        int E) {
    __shared__ __align__(16) float sm_w[WARPS_PER_BLOCK][5 * MULC];  // 5120 B
    __shared__ __align__(16) float sm_o[WARPS_PER_BLOCK][ROWF];
    __shared__ __align__(8)  uint64_t sm_mbar;

    const int tid  = threadIdx.x;
    const int wb   = tid >> 5;
    const int lane = tid & 31;
    const long long e0 = (long long)blockIdx.x * WARPS_PER_BLOCK;
    const int nEdges = (int)min((long long)WARPS_PER_BLOCK, (long long)E - e0);

    const uint32_t mbar = smem_u32(&sm_mbar);

    // Init mbarrier, then issue ONE bulk copy of the block's weight slab.
    if (tid == 0) {
        asm volatile("mbarrier.init.shared.b64 [%0], 1;" :: "r"(mbar) : "memory");
    }
    __syncthreads();
    if (tid == 0) {
        const uint32_t bytes = (uint32_t)nEdges * WBYTES;
        asm volatile("mbarrier.arrive.expect_tx.shared.b64 _, [%0], %1;"
                     :: "r"(mbar), "r"(bytes) : "memory");
        const float* src = edge_weight + e0 * (5 * MULC);
        asm volatile(
            "cp.async.bulk.shared::cluster.global.mbarrier::complete_tx::bytes "
            "[%0], [%1], %2, [%3];"
            :: "r"(smem_u32(&sm_w[0][0])), "l"(src), "r"(bytes), "r"(mbar)
            : "memory");
    }

    // Per-warp scalar loads overlap the TMA weight fetch.
    const long long e = e0 + wb;
    const bool active = (wb < nEdges);

    int s = 0, d = 0;
    float a0 = 0.f, a1x = 0.f, a1y = 0.f, a1z = 0.f;
    float xs0 = 0.f, x1a = 0.f, x1b = 0.f, x1c = 0.f;

    if (active) {
        s = __ldg(edge_src + e);
        d = __ldg(edge_dst + e);
        const float4 a = __ldg(reinterpret_cast<const float4*>(edge_attr) + e);
        a0 = a.x; a1x = a.y; a1y = a.z; a1z = a.w;

        const float* xrow = x + (long long)s * (4 * MULC);
        xs0 = __ldg(xrow + lane);
        x1a = __ldg(xrow + MULC + 3 * lane + 0);
        x1b = __ldg(xrow + MULC + 3 * lane + 1);
        x1c = __ldg(xrow + MULC + 3 * lane + 2);
    }

    // Wait for the weight slab (acquire orders the LDS below).
    {
        uint32_t done;
        asm volatile(
            "{\n\t"
            ".reg .pred p;\n\t"
            "mbarrier.try_wait.parity.acquire.cta.shared::cta.b64 p, [%1], 0;\n\t"
            "selp.b32 %0, 1, 0, p;\n\t"
            "}"
            : "=r"(done) : "r"(mbar) : "memory");
        if (!done) {
            asm volatile(
                "{\n\t"
                ".reg .pred P1;\n\t"
                "WAIT_LOOP_%=:\n\t"
                "mbarrier.try_wait.parity.acquire.cta.shared::cta.b64 P1, [%0], 0, 0x989680;\n\t"
                "@P1 bra.uni WAIT_DONE_%=;\n\t"
                "bra.uni WAIT_LOOP_%=;\n\t"
                "WAIT_DONE_%=:\n\t"
                "}"
                :: "r"(mbar) : "memory");
        }
    }

    if (!active) return;

    // Conflict-free LDS: bank = (wb*160 + j*32 + lane) % 32 — distinct per lane.
    const float* wrow = sm_w[wb];
    const float w0 = wrow[0 * MULC + lane];
    const float w1 = wrow[1 * MULC + lane];
    const float w2 = wrow[2 * MULC + lane];
    const float w3 = wrow[3 * MULC + lane];
    const float w4 = wrow[4 * MULC + lane];

    const float INV_SQRT3 = 0.5773502691896258f;
    const float INV_SQRT2 = 0.7071067811865476f;

    const float o0  = w0 * xs0 * a0;
    const float w1x = w1 * xs0;
    const float o1x = w1x * a1x, o1y = w1x * a1y, o1z = w1x * a1z;
    const float w2a = w2 * a0;
    const float o2x = w2a * x1a, o2y = w2a * x1b, o2z = w2a * x1c;
    const float dot = x1a * a1x + x1b * a1y + x1c * a1z;
    const float o3  = w3 * dot * INV_SQRT3;
    const float cx  = x1b * a1z - x1c * a1y;
    const float cy  = x1c * a1x - x1a * a1z;
    const float cz  = x1a * a1y - x1b * a1x;
    const float w4s = w4 * INV_SQRT2;
    const float o4x = w4s * cx, o4y = w4s * cy, o4z = w4s * cz;

    // Stage the 352-float row (stride-3: gcd(3,32)=1 -> conflict-free)
    float* r = sm_o[wb];
    r[lane]                = o0;
    r[MULC + 3 * lane + 0] = o1x;
    r[MULC + 3 * lane + 1] = o1y;
    r[MULC + 3 * lane + 2] = o1z;
    r[128  + 3 * lane + 0] = o2x;
    r[128  + 3 * lane + 1] = o2y;
    r[128  + 3 * lane + 2] = o2z;
    r[224  + lane]         = o3;
    r[256  + 3 * lane + 0] = o4x;
    r[256  + 3 * lane + 1] = o4y;
    r[256  + 3 * lane + 2] = o4z;
    __syncwarp();

    // TMA bulk-reduce: engine reads smem row, f32-adds into out[dst].
    if (lane == 0) {
        asm volatile("fence.proxy.async.shared::cta;" ::: "memory");
        float*   gptr  = out + (long long)d * ROWF;
        uint32_t saddr = smem_u32(r);
        asm volatile(
            "cp.reduce.async.bulk.global.shared::cta.bulk_group.add.f32 "
            "[%0], [%1], %2;"
            :: "l"(gptr), "r"(saddr), "r"((int)(ROWF * sizeof(float)))
            : "memory");
        asm volatile("cp.async.bulk.commit_group;" ::: "memory");
        asm volatile("cp.async.bulk.wait_group 0;" ::: "memory");
    }
}

extern "C" void kernel_launch(void* const* d_in, const int* in_sizes, int n_in,
                              void* d_out, int out_size) {
    const float* x           = (const float*)d_in[0];
    const float* edge_attr   = (const float*)d_in[1];
    const float* edge_weight = (const float*)d_in[2];
    const int*   edge_dst    = (const int*)d_in[3];
    const int*   edge_src    = (const int*)d_in[4];
    float* out = (float*)d_out;

    const int E = in_sizes[3];

    int n4 = out_size / 4;
    tps_zero_kernel<<<(n4 + 255) / 256, 256>>>((float4*)out, n4);

    int blocks = (E + WARPS_PER_BLOCK - 1) / WARPS_PER_BLOCK;
    tps_scatter_kernel<<<blocks, WARPS_PER_BLOCK * 32>>>(
        x, edge_attr, edge_weight, edge_dst, edge_src, out, E);
}